// round 15
// baseline (speedup 1.0000x reference)
#include <cuda_runtime.h>
#include <math_constants.h>

// One float per (batch, grid cell): g_cells[batch*16 + cell].
__device__ float g_cells[128 * 4 * 4];

// ---------------------------------------------------------------------------
// Kernel 1: SINGLE-WAVE persistent shape. 1024 blocks x 256 threads, each
// block sums TWO adjacent 128x128 cells (cells 2*bid and 2*bid+1 share a
// batch: cell pairs never straddle a batch since 16 cells/batch is even).
// 1024 blocks <= ~1184 concurrent slots -> all resident from t=0, no wave
// transition, one drain. Loads interleaved across the two cells: 32
// independent __ldcs float4 loads per thread (evict-first won its A/B).
// Thread t: c4 = t&31 (float4 col), r0 = t>>5, rows r0+8i.
// ---------------------------------------------------------------------------
__global__ __launch_bounds__(256) void cell_reduce_kernel(const float* __restrict__ x) {
    const int bid   = blockIdx.x;          // 0..1023
    const int cell0 = bid * 2;             // global cell index (batch*16+cell)
    const int batch = cell0 >> 4;
    const int c     = cell0 & 15;          // first cell within batch (even)
    const int gr0   = c >> 2, gc0 = c & 3;
    const int c1    = c + 1;
    const int gr1   = c1 >> 2, gc1 = c1 & 3;

    const int t  = threadIdx.x;            // 0..255
    const int c4 = t & 31;
    const int r0 = t >> 5;                 // 0..7

    const float4* __restrict__ p =
        reinterpret_cast<const float4*>(x) + (size_t)batch * 65536;
    const int base0 = gr0 * (128 * 128) + gc0 * 32;   // float4 units
    const int base1 = gr1 * (128 * 128) + gc1 * 32;

    float s0 = 0.0f, s1 = 0.0f;
    #pragma unroll
    for (int i = 0; i < 16; i++) {
        const int roff = (r0 + 8 * i) * 128 + c4;
        const float4 a = __ldcs(&p[base0 + roff]);
        const float4 b = __ldcs(&p[base1 + roff]);
        s0 += (a.x + a.y) + (a.z + a.w);
        s1 += (b.x + b.y) + (b.z + b.w);
    }

    #pragma unroll
    for (int o = 16; o > 0; o >>= 1) {
        s0 += __shfl_xor_sync(0xffffffffu, s0, o);
        s1 += __shfl_xor_sync(0xffffffffu, s1, o);
    }

    __shared__ float ws0[8], ws1[8];
    if ((t & 31) == 0) { ws0[t >> 5] = s0; ws1[t >> 5] = s1; }
    __syncthreads();

    if (t == 0) {
        g_cells[cell0]     = (ws0[0] + ws0[1]) + (ws0[2] + ws0[3])
                           + (ws0[4] + ws0[5]) + (ws0[6] + ws0[7]);
        g_cells[cell0 + 1] = (ws1[0] + ws1[1]) + (ws1[2] + ws1[3])
                           + (ws1[4] + ws1[5]) + (ws1[6] + ws1[7]);
        __threadfence();                   // publish before PDL completion
    }
    cudaTriggerProgrammaticLaunchCompletion();
}

// ---------------------------------------------------------------------------
// Kernel 2 (PDL secondary, unchanged from R14 winner): spins up concurrently,
// gridsync waits for kernel 1 to drain, then one thread per batch does
// window-sum + first-occurrence argmax and writes float (row, col).
// Mean /16384 skipped: uniform positive scale, argmax-invariant.
// ---------------------------------------------------------------------------
__global__ __launch_bounds__(128) void select_kernel(float* __restrict__ out) {
    cudaGridDependencySynchronize();

    const int b = threadIdx.x;             // one batch per thread
    float cells[16];
    #pragma unroll
    for (int i = 0; i < 16; i++) cells[i] = g_cells[b * 16 + i];

    float best = -CUDART_INF_F;
    int   bi   = 0;
    #pragma unroll
    for (int r = 0; r < 2; r++) {
        #pragma unroll
        for (int cc = 0; cc < 2; cc++) {
            float w = 0.0f;
            #pragma unroll
            for (int dr = 0; dr < 3; dr++)
                #pragma unroll
                for (int dc = 0; dc < 3; dc++)
                    w += cells[(r + dr) * 4 + (cc + dc)];
            if (w > best) { best = w; bi = r * 2 + cc; }   // first-occurrence
        }
    }
    out[b * 2 + 0] = (float)(bi >> 1);     // row (float output dtype)
    out[b * 2 + 1] = (float)(bi & 1);      // col
}

extern "C" void kernel_launch(void* const* d_in, const int* in_sizes, int n_in,
                              void* d_out, int out_size) {
    const float* x = (const float*)d_in[0];
    float* out = (float*)d_out;

    cell_reduce_kernel<<<1024, 256>>>(x);

    cudaLaunchConfig_t cfg = {};
    cfg.gridDim  = dim3(1, 1, 1);
    cfg.blockDim = dim3(128, 1, 1);
    cudaLaunchAttribute attr[1];
    attr[0].id = cudaLaunchAttributeProgrammaticStreamSerialization;
    attr[0].val.programmaticStreamSerializationAllowed = 1;
    cfg.attrs    = attr;
    cfg.numAttrs = 1;
    cudaLaunchKernelEx(&cfg, select_kernel, out);
}

// round 16
// speedup vs baseline: 1.1379x; 1.1379x over previous
#include <cuda_runtime.h>
#include <math_constants.h>

// One float per (batch, grid cell): index == blockIdx.x of kernel 1.
__device__ float g_cells[128 * 4 * 4];

// ---------------------------------------------------------------------------
// Kernel 1: one block per grid cell — the best-measured phase-1 shape
// (R14 winner, 25.1us). 2048 blocks x 256 threads, 8 blocks/SM, 1.73 waves
// (wave 2 work-steals and self-balances; single-wave variant R15 regressed).
// __ldcs evict-first won its controlled A/B (R10 25.6 vs R11 28.8).
// Each block privately sums its 128x128 cell; thread t: c4 = t&31 (float4
// col), r0 = t>>5, rows r0+8i -> 16 independent coalesced loads (MLP 16).
// ---------------------------------------------------------------------------
__global__ __launch_bounds__(256) void cell_reduce_kernel(const float* __restrict__ x) {
    const int bid   = blockIdx.x;      // batch*16 + gr*4 + gc
    const int batch = bid >> 4;
    const int cell  = bid & 15;
    const int gr    = cell >> 2;
    const int gc    = cell & 3;

    const int t  = threadIdx.x;        // 0..255
    const int c4 = t & 31;
    const int r0 = t >> 5;             // 0..7

    const float4* __restrict__ p =
        reinterpret_cast<const float4*>(x) + (size_t)batch * 65536;
    const int cellbase = gr * (128 * 128) + gc * 32;   // float4 units

    float s = 0.0f;
    #pragma unroll
    for (int i = 0; i < 16; i++) {
        const float4 v = __ldcs(&p[cellbase + (r0 + 8 * i) * 128 + c4]);
        s += (v.x + v.y) + (v.z + v.w);
    }

    #pragma unroll
    for (int o = 16; o > 0; o >>= 1)
        s += __shfl_xor_sync(0xffffffffu, s, o);

    __shared__ float ws[8];
    if ((t & 31) == 0) ws[t >> 5] = s;
    __syncthreads();

    if (t == 0) {
        g_cells[bid] = (ws[0] + ws[1]) + (ws[2] + ws[3])
                     + (ws[4] + ws[5]) + (ws[6] + ws[7]);
        __threadfence();               // publish before signaling completion
    }
    // PDL: signal this block's completion so the dependent kernel can start.
    cudaTriggerProgrammaticLaunchCompletion();
}

// ---------------------------------------------------------------------------
// Kernel 2 (PDL secondary): launches concurrently with kernel 1's tail;
// gridsync blocks until ALL kernel-1 blocks are done, then one thread per
// batch: 16 cell sums -> four 3x3 window sums -> first-occurrence argmax ->
// float (row, col). Mean /16384 skipped: uniform positive, argmax-safe.
// ---------------------------------------------------------------------------
__global__ __launch_bounds__(128) void select_kernel(float* __restrict__ out) {
    cudaGridDependencySynchronize();   // wait for kernel 1 to fully drain

    const int b = threadIdx.x;         // one batch per thread (grid = 1x128)
    float cells[16];
    #pragma unroll
    for (int i = 0; i < 16; i++) cells[i] = g_cells[b * 16 + i];

    float best = -CUDART_INF_F;
    int   bi   = 0;
    #pragma unroll
    for (int r = 0; r < 2; r++) {
        #pragma unroll
        for (int c = 0; c < 2; c++) {
            float w = 0.0f;
            #pragma unroll
            for (int dr = 0; dr < 3; dr++)
                #pragma unroll
                for (int dc = 0; dc < 3; dc++)
                    w += cells[(r + dr) * 4 + (c + dc)];
            if (w > best) { best = w; bi = r * 2 + c; }  // first-occurrence
        }
    }
    out[b * 2 + 0] = (float)(bi >> 1);  // row (float output dtype)
    out[b * 2 + 1] = (float)(bi & 1);   // col
}

extern "C" void kernel_launch(void* const* d_in, const int* in_sizes, int n_in,
                              void* d_out, int out_size) {
    const float* x = (const float*)d_in[0];
    float* out = (float*)d_out;

    cell_reduce_kernel<<<2048, 256>>>(x);

    // Launch select with Programmatic Stream Serialization: it may begin
    // while kernel 1 is still running; the gridsync inside provides the
    // real dependency. Graph capture preserves this as a programmatic edge.
    cudaLaunchConfig_t cfg = {};
    cfg.gridDim  = dim3(1, 1, 1);
    cfg.blockDim = dim3(128, 1, 1);
    cudaLaunchAttribute attr[1];
    attr[0].id = cudaLaunchAttributeProgrammaticStreamSerialization;
    attr[0].val.programmaticStreamSerializationAllowed = 1;
    cfg.attrs    = attr;
    cfg.numAttrs = 1;
    cudaLaunchKernelEx(&cfg, select_kernel, out);
}